// round 5
// baseline (speedup 1.0000x reference)
#include <cuda_runtime.h>
#include <cuda_bf16.h>
#include <cstdint>

#define B_    32
#define VLEN_ 2048
#define H_    1024
#define DIM_  1024
#define C_    32
#define KC    1088              // 1024 (value) + 32 (conv feat) + 32 zero pad
#define M_    (B_*VLEN_)        // 65536

// ---------------- scratch (device globals: no runtime allocation) ----------------
__device__ __nv_bfloat16 g_valcat[(size_t)M_*KC];    // [65536][1088] bf16  (~142 MB)
__device__ __nv_bfloat16 g_wcat[(size_t)DIM_*KC];    // [1024][1088] bf16
__device__ float g_qbias[B_*DIM_];                   // qp[b,d] + bias[d]
__device__ float g_score[M_];
__device__ float g_attn[M_];
__device__ float g_context[B_*H_];

__device__ __forceinline__ uint32_t smem_u32(const void* p){
    return (uint32_t)__cvta_generic_to_shared(p);
}

// ---------------- prep: A matrix = [value(bf16) | conv_feat(bf16) | 0] ----------------
__global__ void build_valcat(const float* __restrict__ value,
                             const float* __restrict__ prev_attn,
                             const float* __restrict__ conv_w,
                             const float* __restrict__ conv_b) {
    int t = blockIdx.x*256 + threadIdx.x;               // one 16B chunk each
    const int CHUNKS = KC/8;                            // 136
    if (t >= M_*CHUNKS) return;
    int bv = t / CHUNKS, chunk = t % CHUNKS;
    __align__(16) __nv_bfloat16 o[8];
    if (chunk < 128) {
        const float4* s = reinterpret_cast<const float4*>(value + (size_t)bv*H_ + chunk*8);
        float4 x = s[0], y = s[1];
        o[0]=__float2bfloat16(x.x); o[1]=__float2bfloat16(x.y);
        o[2]=__float2bfloat16(x.z); o[3]=__float2bfloat16(x.w);
        o[4]=__float2bfloat16(y.x); o[5]=__float2bfloat16(y.y);
        o[6]=__float2bfloat16(y.z); o[7]=__float2bfloat16(y.w);
    } else if (chunk < 132) {
        int b = bv >> 11, v = bv & 2047;
        float pm = (v > 0)        ? prev_attn[b*VLEN_ + v - 1] : 0.f;
        float pc =                  prev_attn[b*VLEN_ + v];
        float pp = (v < VLEN_-1)  ? prev_attn[b*VLEN_ + v + 1] : 0.f;
        int c0 = (chunk-128)*8;
        #pragma unroll
        for (int j = 0; j < 8; j++) {
            int c = c0 + j;
            float cf = conv_w[c*3+0]*pm + conv_w[c*3+1]*pc + conv_w[c*3+2]*pp + conv_b[c];
            o[j] = __float2bfloat16(cf);
        }
    } else {
        #pragma unroll
        for (int j = 0; j < 8; j++) o[j] = __float2bfloat16(0.f);
    }
    *reinterpret_cast<uint4*>(g_valcat + (size_t)bv*KC + chunk*8) = *reinterpret_cast<uint4*>(o);
}

// ---------------- prep: B matrix = [w_v | w_loc | 0] ----------------
__global__ void build_wcat(const float* __restrict__ w_v, const float* __restrict__ w_loc) {
    int t = blockIdx.x*256 + threadIdx.x;
    const int CHUNKS = KC/8;
    if (t >= DIM_*CHUNKS) return;
    int d = t / CHUNKS, chunk = t % CHUNKS;
    __align__(16) __nv_bfloat16 o[8];
    if (chunk < 128) {
        const float* s = w_v + (size_t)d*H_ + chunk*8;
        #pragma unroll
        for (int j = 0; j < 8; j++) o[j] = __float2bfloat16(s[j]);
    } else if (chunk < 132) {
        const float* s = w_loc + (size_t)d*C_ + (chunk-128)*8;
        #pragma unroll
        for (int j = 0; j < 8; j++) o[j] = __float2bfloat16(s[j]);
    } else {
        #pragma unroll
        for (int j = 0; j < 8; j++) o[j] = __float2bfloat16(0.f);
    }
    *reinterpret_cast<uint4*>(g_wcat + (size_t)d*KC + chunk*8) = *reinterpret_cast<uint4*>(o);
}

// ---------------- prep: qbias[b,d] = query[b] . w_q[d] + bias[d] (fp32 exact) ----------------
__global__ void qbias_kernel(const float* __restrict__ query,
                             const float* __restrict__ w_q,
                             const float* __restrict__ bias) {
    int b = blockIdx.y;
    int warp = threadIdx.x >> 5, lane = threadIdx.x & 31;
    int d = blockIdx.x*8 + warp;
    const float* q = query + b*H_;
    const float* w = w_q + (size_t)d*H_;
    float acc = 0.f;
    for (int h = lane; h < H_; h += 32) acc += q[h]*w[h];
    #pragma unroll
    for (int o = 16; o; o >>= 1) acc += __shfl_xor_sync(0xffffffffu, acc, o);
    if (!lane) g_qbias[b*DIM_ + d] = acc + bias[d];
}

__global__ void zero_score() {
    int t = blockIdx.x*256 + threadIdx.x;
    if (t < M_) g_score[t] = 0.f;
}

// ---------------- fused GEMM + tanh + score reduction (HMMA path) ----------------
// C[m,n] = sum_k A[m,k]*B[n,k] ; score[m] += sum_n tanh(C + qbias[b,n]) * w_score[n]
// BM=128, BN=256, BK=32, 8 warps (2 along M x 4 along N), warp tile 64x64.
// 4-stage cp.async pipeline, 122KB dynamic smem, 1 CTA/SM.
#define BM 128
#define BN 256
#define BK 32
#define STG 4
#define KPAD 40   // padded smem row (bf16 elems)

#define A_STG_ELEMS (BM*KPAD)            // 5120
#define B_STG_ELEMS (BN*KPAD)            // 10240
#define SM_A_OFF 0
#define SM_B_OFF (STG*A_STG_ELEMS*2)                    // 40960
#define SM_QB_OFF (SM_B_OFF + STG*B_STG_ELEMS*2)        // 122880
#define SM_WS_OFF (SM_QB_OFF + BN*4)                    // 123904
#define SMEM_TOTAL_GEMM (SM_WS_OFF + BN*4)              // 124928

__device__ __forceinline__ void mma16816(float* c, const uint32_t* a, uint32_t b0, uint32_t b1) {
    asm volatile("mma.sync.aligned.m16n8k16.row.col.f32.bf16.bf16.f32 "
                 "{%0,%1,%2,%3}, {%4,%5,%6,%7}, {%8,%9}, {%0,%1,%2,%3};"
                 : "+f"(c[0]), "+f"(c[1]), "+f"(c[2]), "+f"(c[3])
                 : "r"(a[0]), "r"(a[1]), "r"(a[2]), "r"(a[3]), "r"(b0), "r"(b1));
}

__global__ __launch_bounds__(256, 1)
void gemm_score_kernel(const float* __restrict__ w_score) {
    extern __shared__ __align__(16) char sm[];
    __nv_bfloat16* As = reinterpret_cast<__nv_bfloat16*>(sm + SM_A_OFF);  // [STG][BM][KPAD]
    __nv_bfloat16* Bs = reinterpret_cast<__nv_bfloat16*>(sm + SM_B_OFF);  // [STG][BN][KPAD]
    float* qb_s = reinterpret_cast<float*>(sm + SM_QB_OFF);
    float* ws_s = reinterpret_cast<float*>(sm + SM_WS_OFF);

    const int t = threadIdx.x;
    const int warp = t >> 5, lane = t & 31;
    const int bn0 = blockIdx.x * BN;   // x fastest -> 4 n-CTAs of one m-block co-resident
    const int bm0 = blockIdx.y * BM;
    const int batch = bm0 >> 11;       // 2048 rows per batch; BM | 2048

    if (t < BN) {
        qb_s[t] = g_qbias[batch*DIM_ + bn0 + t];
        ws_s[t] = w_score[bn0 + t];
    }

    const int lrow = t >> 2;      // 0..63
    const int lch  = t & 3;       // 16B chunk within 64B k-slab
    const __nv_bfloat16* Ag = g_valcat + (size_t)bm0*KC + lch*8;
    const __nv_bfloat16* Bg = g_wcat   + (size_t)bn0*KC + lch*8;

    const int wm = (warp >> 2) * 64;   // 2 warp rows along M
    const int wn = (warp & 3) * 64;    // 4 warp cols along N

    float acc[4][8][4];
    #pragma unroll
    for (int i = 0; i < 4; i++)
        #pragma unroll
        for (int j = 0; j < 8; j++)
            #pragma unroll
            for (int k = 0; k < 4; k++) acc[i][j][k] = 0.f;

    auto load_stage = [&](int s) {
        int slot = s % STG;
        int k0 = s * BK;
        __nv_bfloat16* Ad = As + slot*A_STG_ELEMS;
        __nv_bfloat16* Bd = Bs + slot*B_STG_ELEMS;
        #pragma unroll
        for (int i = 0; i < 2; i++) {
            int r = lrow + i*64;
            uint32_t d = smem_u32(Ad + r*KPAD + lch*8);
            asm volatile("cp.async.cg.shared.global [%0], [%1], 16;\n"
                         :: "r"(d), "l"(Ag + (size_t)r*KC + k0));
        }
        #pragma unroll
        for (int i = 0; i < 4; i++) {
            int r = lrow + i*64;
            uint32_t d = smem_u32(Bd + r*KPAD + lch*8);
            asm volatile("cp.async.cg.shared.global [%0], [%1], 16;\n"
                         :: "r"(d), "l"(Bg + (size_t)r*KC + k0));
        }
        asm volatile("cp.async.commit_group;\n");
    };

    const int NK = KC / BK;  // 34
    load_stage(0); load_stage(1); load_stage(2);

    for (int s = 0; s < NK; ++s) {
        if (s + 2 < NK)      { asm volatile("cp.async.wait_group 2;\n"); }
        else if (s + 1 < NK) { asm volatile("cp.async.wait_group 1;\n"); }
        else                 { asm volatile("cp.async.wait_group 0;\n"); }
        __syncthreads();

        int slot = s % STG;
        const __nv_bfloat16* Asl = As + slot*A_STG_ELEMS;
        const __nv_bfloat16* Bsl = Bs + slot*B_STG_ELEMS;
        const int g = lane >> 3, idx = lane & 7;

        #pragma unroll
        for (int kk = 0; kk < 2; ++kk) {
            const int kb = kk*16;
            uint32_t a[4][4];
            #pragma unroll
            for (int mi = 0; mi < 4; mi++) {
                int row = wm + mi*16 + idx + 8*(g & 1);
                int col = kb + 8*(g >> 1);
                uint32_t addr = smem_u32(Asl + row*KPAD + col);
                asm volatile("ldmatrix.sync.aligned.m8n8.x4.shared.b16 {%0,%1,%2,%3}, [%4];"
                             : "=r"(a[mi][0]), "=r"(a[mi][1]), "=r"(a[mi][2]), "=r"(a[mi][3])
                             : "r"(addr));
            }
            uint32_t bfrag[4][4];
            #pragma unroll
            for (int ni = 0; ni < 4; ni++) {
                int row = wn + ni*16 + idx + 8*(g >> 1);
                int col = kb + 8*(g & 1);
                uint32_t addr = smem_u32(Bsl + row*KPAD + col);
                asm volatile("ldmatrix.sync.aligned.m8n8.x4.shared.b16 {%0,%1,%2,%3}, [%4];"
                             : "=r"(bfrag[ni][0]), "=r"(bfrag[ni][1]), "=r"(bfrag[ni][2]), "=r"(bfrag[ni][3])
                             : "r"(addr));
            }
            #pragma unroll
            for (int mi = 0; mi < 4; mi++)
                #pragma unroll
                for (int ni = 0; ni < 4; ni++) {
                    mma16816(acc[mi][ni*2+0], a[mi], bfrag[ni][0], bfrag[ni][1]);
                    mma16816(acc[mi][ni*2+1], a[mi], bfrag[ni][2], bfrag[ni][3]);
                }
        }
        __syncthreads();
        if (s + 3 < NK) load_stage(s + 3);
    }

    // epilogue: tanh + weighted reduce over this CTA's 256 d-columns
    #pragma unroll
    for (int mi = 0; mi < 4; mi++) {
        float s0 = 0.f, s1 = 0.f;   // rows (lane>>2) and (lane>>2)+8 of this m16 frag
        #pragma unroll
        for (int j = 0; j < 8; j++) {
            int nc = wn + j*8 + 2*(lane & 3);
            float qb0 = qb_s[nc], qb1 = qb_s[nc+1];
            float w0 = ws_s[nc],  w1 = ws_s[nc+1];
            s0 += tanhf(acc[mi][j][0] + qb0)*w0 + tanhf(acc[mi][j][1] + qb1)*w1;
            s1 += tanhf(acc[mi][j][2] + qb0)*w0 + tanhf(acc[mi][j][3] + qb1)*w1;
        }
        s0 += __shfl_xor_sync(0xffffffffu, s0, 1);
        s0 += __shfl_xor_sync(0xffffffffu, s0, 2);
        s1 += __shfl_xor_sync(0xffffffffu, s1, 1);
        s1 += __shfl_xor_sync(0xffffffffu, s1, 2);
        if ((lane & 3) == 0) {
            int m0 = bm0 + wm + mi*16 + (lane >> 2);
            atomicAdd(&g_score[m0],     s0);
            atomicAdd(&g_score[m0 + 8], s1);
        }
    }
}

// ---------------- sigmoid + normalize -> attn (also zero context) ----------------
__global__ void normalize_kernel(const float* __restrict__ b_score, float* __restrict__ attn_out,
                                 int write_attn) {
    int b = blockIdx.x, t = threadIdx.x;     // 256 threads, 2048 elems
    __shared__ float red[256];
    for (int h = t; h < H_; h += 256) g_context[b*H_ + h] = 0.f;
    float bs = b_score[0];
    float sv[8];
    float local = 0.f;
    #pragma unroll
    for (int i = 0; i < 8; i++) {
        float x = g_score[b*VLEN_ + t + i*256] + bs;
        float s = 1.f / (1.f + __expf(-x));
        sv[i] = s; local += s;
    }
    red[t] = local; __syncthreads();
    #pragma unroll
    for (int o = 128; o; o >>= 1) { if (t < o) red[t] += red[t+o]; __syncthreads(); }
    float inv = 1.f / red[0];
    #pragma unroll
    for (int i = 0; i < 8; i++) {
        float a = sv[i] * inv;
        g_attn[b*VLEN_ + t + i*256] = a;
        if (write_attn) attn_out[b*VLEN_ + t + i*256] = a;
    }
}

// ---------------- context[b,h] = sum_v attn[b,v] * value[b,v,h] ----------------
__global__ void context_kernel(const float* __restrict__ value) {
    int hc = blockIdx.x, b = blockIdx.y, vs = blockIdx.z;   // (4, B, 8)
    int h = hc*256 + threadIdx.x;
    __shared__ float a_s[256];
    a_s[threadIdx.x] = g_attn[b*VLEN_ + vs*256 + threadIdx.x];
    __syncthreads();
    const float* vp = value + ((size_t)b*VLEN_ + vs*256)*H_ + h;
    float acc = 0.f;
    #pragma unroll 8
    for (int v = 0; v < 256; v++) acc += a_s[v] * vp[(size_t)v*H_];
    atomicAdd(&g_context[b*H_ + h], acc);
}

// ---------------- output[b,h] = w_out[h] . [context | query] + b_out[h] ----------------
__global__ void output_kernel(const float* __restrict__ w_out, const float* __restrict__ b_out,
                              const float* __restrict__ query, float* __restrict__ out) {
    int b = blockIdx.y;
    int warp = threadIdx.x >> 5, lane = threadIdx.x & 31;
    int h = blockIdx.x*8 + warp;
    const float* wr = w_out + (size_t)h*(2*H_);
    const float* ctx = g_context + b*H_;
    const float* q = query + b*H_;
    float acc = 0.f;
    for (int k = lane; k < H_; k += 32) acc += wr[k]*ctx[k];
    for (int k = lane; k < H_; k += 32) acc += wr[H_+k]*q[k];
    #pragma unroll
    for (int o = 16; o; o >>= 1) acc += __shfl_xor_sync(0xffffffffu, acc, o);
    if (!lane) out[b*H_ + h] = acc + b_out[h];
}

// ---------------- launch ----------------
extern "C" void kernel_launch(void* const* d_in, const int* in_sizes, int n_in,
                              void* d_out, int out_size) {
    const float* query     = (const float*)d_in[0];
    const float* value     = (const float*)d_in[1];
    const float* prev_attn = (const float*)d_in[2];
    const float* conv_w    = (const float*)d_in[3];
    const float* conv_b    = (const float*)d_in[4];
    const float* w_loc     = (const float*)d_in[5];
    const float* w_q       = (const float*)d_in[6];
    const float* w_v       = (const float*)d_in[7];
    const float* bias      = (const float*)d_in[8];
    const float* w_score   = (const float*)d_in[9];
    const float* b_score   = (const float*)d_in[10];
    const float* w_out     = (const float*)d_in[11];
    const float* b_out     = (const float*)d_in[12];
    float* out = (float*)d_out;

    (void)in_sizes; (void)n_in;

    cudaFuncSetAttribute(gemm_score_kernel,
                         cudaFuncAttributeMaxDynamicSharedMemorySize, SMEM_TOTAL_GEMM);

    build_valcat<<< (M_*(KC/8))/256, 256 >>>(value, prev_attn, conv_w, conv_b);
    build_wcat<<< (DIM_*(KC/8) + 255)/256, 256 >>>(w_v, w_loc);
    qbias_kernel<<< dim3(DIM_/8, B_), 256 >>>(query, w_q, bias);
    zero_score<<< M_/256, 256 >>>();
    gemm_score_kernel<<< dim3(DIM_/BN, M_/BM), 256, SMEM_TOTAL_GEMM >>>(w_score);

    int write_attn = (out_size >= B_*H_ + M_) ? 1 : 0;   // output first, then attn
    normalize_kernel<<< B_, 256 >>>(b_score, out + B_*H_, write_attn);
    context_kernel<<< dim3(H_/256, B_, VLEN_/256), 256 >>>(value);
    output_kernel<<< dim3(H_/8, B_), 256 >>>(w_out, b_out, query, out);
}

// round 6
// speedup vs baseline: 1.1671x; 1.1671x over previous
#include <cuda_runtime.h>
#include <cuda_bf16.h>
#include <cstdint>

#define B_    32
#define VLEN_ 2048
#define H_    1024
#define DIM_  1024
#define C_    32
#define KC    1088              // 1024 (value) + 32 (conv feat) + 32 zero pad
#define M_    (B_*VLEN_)        // 65536

// ---------------- scratch (device globals: no runtime allocation) ----------------
__device__ __nv_bfloat16 g_valcat[(size_t)M_*KC];    // [65536][1088] bf16  (~142 MB)
__device__ __nv_bfloat16 g_wcat[(size_t)DIM_*KC];    // [1024][1088] bf16
__device__ float g_qbias[B_*DIM_];                   // qp[b,d] + bias[d]
__device__ float g_score[M_];
__device__ float g_attn[M_];
__device__ float g_context[B_*H_];

__device__ __forceinline__ uint32_t smem_u32(const void* p){
    return (uint32_t)__cvta_generic_to_shared(p);
}

// -------- prep: A matrix = [value(bf16) | conv_feat(bf16) | 0]; also zeroes g_score --------
__global__ void build_valcat(const float* __restrict__ value,
                             const float* __restrict__ prev_attn,
                             const float* __restrict__ conv_w,
                             const float* __restrict__ conv_b) {
    int t = blockIdx.x*256 + threadIdx.x;               // one 16B chunk each
    const int CHUNKS = KC/8;                            // 136
    if (t < M_) g_score[t] = 0.f;                       // fused zero_score
    if (t >= M_*CHUNKS) return;
    int bv = t / CHUNKS, chunk = t % CHUNKS;
    __align__(16) __nv_bfloat16 o[8];
    if (chunk < 128) {
        const float4* s = reinterpret_cast<const float4*>(value + (size_t)bv*H_ + chunk*8);
        float4 x = s[0], y = s[1];
        o[0]=__float2bfloat16(x.x); o[1]=__float2bfloat16(x.y);
        o[2]=__float2bfloat16(x.z); o[3]=__float2bfloat16(x.w);
        o[4]=__float2bfloat16(y.x); o[5]=__float2bfloat16(y.y);
        o[6]=__float2bfloat16(y.z); o[7]=__float2bfloat16(y.w);
    } else if (chunk < 132) {
        int b = bv >> 11, v = bv & 2047;
        float pm = (v > 0)        ? prev_attn[b*VLEN_ + v - 1] : 0.f;
        float pc =                  prev_attn[b*VLEN_ + v];
        float pp = (v < VLEN_-1)  ? prev_attn[b*VLEN_ + v + 1] : 0.f;
        int c0 = (chunk-128)*8;
        #pragma unroll
        for (int j = 0; j < 8; j++) {
            int c = c0 + j;
            float cf = conv_w[c*3+0]*pm + conv_w[c*3+1]*pc + conv_w[c*3+2]*pp + conv_b[c];
            o[j] = __float2bfloat16(cf);
        }
    } else {
        #pragma unroll
        for (int j = 0; j < 8; j++) o[j] = __float2bfloat16(0.f);
    }
    *reinterpret_cast<uint4*>(g_valcat + (size_t)bv*KC + chunk*8) = *reinterpret_cast<uint4*>(o);
}

// ---------------- prep: B matrix = [w_v | w_loc | 0] ----------------
__global__ void build_wcat(const float* __restrict__ w_v, const float* __restrict__ w_loc) {
    int t = blockIdx.x*256 + threadIdx.x;
    const int CHUNKS = KC/8;
    if (t >= DIM_*CHUNKS) return;
    int d = t / CHUNKS, chunk = t % CHUNKS;
    __align__(16) __nv_bfloat16 o[8];
    if (chunk < 128) {
        const float* s = w_v + (size_t)d*H_ + chunk*8;
        #pragma unroll
        for (int j = 0; j < 8; j++) o[j] = __float2bfloat16(s[j]);
    } else if (chunk < 132) {
        const float* s = w_loc + (size_t)d*C_ + (chunk-128)*8;
        #pragma unroll
        for (int j = 0; j < 8; j++) o[j] = __float2bfloat16(s[j]);
    } else {
        #pragma unroll
        for (int j = 0; j < 8; j++) o[j] = __float2bfloat16(0.f);
    }
    *reinterpret_cast<uint4*>(g_wcat + (size_t)d*KC + chunk*8) = *reinterpret_cast<uint4*>(o);
}

// ---------------- prep: qbias[b,d] = query[b] . w_q[d] + bias[d] (fp32 exact) ----------------
__global__ void qbias_kernel(const float* __restrict__ query,
                             const float* __restrict__ w_q,
                             const float* __restrict__ bias) {
    int b = blockIdx.y;
    int warp = threadIdx.x >> 5, lane = threadIdx.x & 31;
    int d = blockIdx.x*8 + warp;
    const float* q = query + b*H_;
    const float* w = w_q + (size_t)d*H_;
    float acc = 0.f;
    for (int h = lane; h < H_; h += 32) acc += q[h]*w[h];
    #pragma unroll
    for (int o = 16; o; o >>= 1) acc += __shfl_xor_sync(0xffffffffu, acc, o);
    if (!lane) g_qbias[b*DIM_ + d] = acc + bias[d];
}

// ---------------- fused GEMM + tanh + score reduction (HMMA path) ----------------
// C[m,n] = sum_k A[m,k]*B[n,k] ; score[m] += sum_n tanh(C + qbias[b,n]) * w_score[n]
// BM=128, BN=128, BK=32, 8 warps (4 along M x 2 along N), warp tile 32x64.
// 4-stage cp.async pipeline, one __syncthreads per k-step, 2 CTAs/SM.
#define BM 128
#define BN 128
#define BK 32
#define STG 4
#define KPAD 40   // padded smem row (bf16 elems) -> conflict-free ldmatrix

#define A_STG_ELEMS (BM*KPAD)            // 5120
#define B_STG_ELEMS (BN*KPAD)            // 5120
#define SM_A_OFF 0
#define SM_B_OFF (STG*A_STG_ELEMS*2)                    // 40960
#define SM_QB_OFF (SM_B_OFF + STG*B_STG_ELEMS*2)        // 81920
#define SM_WS_OFF (SM_QB_OFF + BN*4)
#define SMEM_TOTAL_GEMM (SM_WS_OFF + BN*4)              // 82944

__device__ __forceinline__ void mma16816(float* c, const uint32_t* a, uint32_t b0, uint32_t b1) {
    asm volatile("mma.sync.aligned.m16n8k16.row.col.f32.bf16.bf16.f32 "
                 "{%0,%1,%2,%3}, {%4,%5,%6,%7}, {%8,%9}, {%0,%1,%2,%3};"
                 : "+f"(c[0]), "+f"(c[1]), "+f"(c[2]), "+f"(c[3])
                 : "r"(a[0]), "r"(a[1]), "r"(a[2]), "r"(a[3]), "r"(b0), "r"(b1));
}

__global__ __launch_bounds__(256, 2)
void gemm_score_kernel(const float* __restrict__ w_score) {
    extern __shared__ __align__(16) char sm[];
    __nv_bfloat16* As = reinterpret_cast<__nv_bfloat16*>(sm + SM_A_OFF);  // [STG][BM][KPAD]
    __nv_bfloat16* Bs = reinterpret_cast<__nv_bfloat16*>(sm + SM_B_OFF);  // [STG][BN][KPAD]
    float* qb_s = reinterpret_cast<float*>(sm + SM_QB_OFF);
    float* ws_s = reinterpret_cast<float*>(sm + SM_WS_OFF);

    const int t = threadIdx.x;
    const int warp = t >> 5, lane = t & 31;
    const int bn0 = blockIdx.x * BN;   // x fastest -> n-CTAs of one m-block co-resident
    const int bm0 = blockIdx.y * BM;
    const int batch = bm0 >> 11;       // 2048 rows per batch; BM | 2048

    if (t < BN) {
        qb_s[t] = g_qbias[batch*DIM_ + bn0 + t];
        ws_s[t] = w_score[bn0 + t];
    }

    const int lrow = t >> 2;      // 0..63
    const int lch  = t & 3;       // 16B chunk within 64B k-slab
    const __nv_bfloat16* Ag = g_valcat + (size_t)bm0*KC + lch*8;
    const __nv_bfloat16* Bg = g_wcat   + (size_t)bn0*KC + lch*8;

    const int wm = (warp >> 1) * 32;   // 4 warps along M
    const int wn = (warp & 1) * 64;    // 2 warps along N

    float acc[2][8][4];
    #pragma unroll
    for (int i = 0; i < 2; i++)
        #pragma unroll
        for (int j = 0; j < 8; j++)
            #pragma unroll
            for (int k = 0; k < 4; k++) acc[i][j][k] = 0.f;

    auto load_stage = [&](int s) {
        int slot = s % STG;
        int k0 = s * BK;
        __nv_bfloat16* Ad = As + slot*A_STG_ELEMS;
        __nv_bfloat16* Bd = Bs + slot*B_STG_ELEMS;
        #pragma unroll
        for (int i = 0; i < 2; i++) {
            int r = lrow + i*64;
            uint32_t d = smem_u32(Ad + r*KPAD + lch*8);
            asm volatile("cp.async.cg.shared.global [%0], [%1], 16;\n"
                         :: "r"(d), "l"(Ag + (size_t)r*KC + k0));
            uint32_t db = smem_u32(Bd + r*KPAD + lch*8);
            asm volatile("cp.async.cg.shared.global [%0], [%1], 16;\n"
                         :: "r"(db), "l"(Bg + (size_t)r*KC + k0));
        }
        asm volatile("cp.async.commit_group;\n");
    };

    const int NK = KC / BK;  // 34
    load_stage(0); load_stage(1); load_stage(2);

    for (int s = 0; s < NK; ++s) {
        if (s + 2 < NK)      { asm volatile("cp.async.wait_group 2;\n"); }
        else if (s + 1 < NK) { asm volatile("cp.async.wait_group 1;\n"); }
        else                 { asm volatile("cp.async.wait_group 0;\n"); }
        __syncthreads();
        // slot (s+3)%STG == (s-1)%STG: all threads finished computing it before
        // this barrier, so refill is safe; issue loads BEFORE compute for overlap.
        if (s + 3 < NK) load_stage(s + 3);

        int slot = s % STG;
        const __nv_bfloat16* Asl = As + slot*A_STG_ELEMS;
        const __nv_bfloat16* Bsl = Bs + slot*B_STG_ELEMS;
        const int g = lane >> 3, idx = lane & 7;

        #pragma unroll
        for (int kk = 0; kk < 2; ++kk) {
            const int kb = kk*16;
            uint32_t a[2][4];
            #pragma unroll
            for (int mi = 0; mi < 2; mi++) {
                int row = wm + mi*16 + idx + 8*(g & 1);
                int col = kb + 8*(g >> 1);
                uint32_t addr = smem_u32(Asl + row*KPAD + col);
                asm volatile("ldmatrix.sync.aligned.m8n8.x4.shared.b16 {%0,%1,%2,%3}, [%4];"
                             : "=r"(a[mi][0]), "=r"(a[mi][1]), "=r"(a[mi][2]), "=r"(a[mi][3])
                             : "r"(addr));
            }
            uint32_t bfrag[4][4];
            #pragma unroll
            for (int ni = 0; ni < 4; ni++) {
                int row = wn + ni*16 + idx + 8*(g >> 1);
                int col = kb + 8*(g & 1);
                uint32_t addr = smem_u32(Bsl + row*KPAD + col);
                asm volatile("ldmatrix.sync.aligned.m8n8.x4.shared.b16 {%0,%1,%2,%3}, [%4];"
                             : "=r"(bfrag[ni][0]), "=r"(bfrag[ni][1]), "=r"(bfrag[ni][2]), "=r"(bfrag[ni][3])
                             : "r"(addr));
            }
            #pragma unroll
            for (int mi = 0; mi < 2; mi++)
                #pragma unroll
                for (int ni = 0; ni < 4; ni++) {
                    mma16816(acc[mi][ni*2+0], a[mi], bfrag[ni][0], bfrag[ni][1]);
                    mma16816(acc[mi][ni*2+1], a[mi], bfrag[ni][2], bfrag[ni][3]);
                }
        }
    }

    // epilogue: tanh + weighted reduce over this CTA's 128 d-columns
    #pragma unroll
    for (int mi = 0; mi < 2; mi++) {
        float s0 = 0.f, s1 = 0.f;   // rows (lane>>2) and (lane>>2)+8
        #pragma unroll
        for (int j = 0; j < 8; j++) {
            int nc = wn + j*8 + 2*(lane & 3);
            float qb0 = qb_s[nc], qb1 = qb_s[nc+1];
            float w0 = ws_s[nc],  w1 = ws_s[nc+1];
            s0 += tanhf(acc[mi][j][0] + qb0)*w0 + tanhf(acc[mi][j][1] + qb1)*w1;
            s1 += tanhf(acc[mi][j][2] + qb0)*w0 + tanhf(acc[mi][j][3] + qb1)*w1;
        }
        s0 += __shfl_xor_sync(0xffffffffu, s0, 1);
        s0 += __shfl_xor_sync(0xffffffffu, s0, 2);
        s1 += __shfl_xor_sync(0xffffffffu, s1, 1);
        s1 += __shfl_xor_sync(0xffffffffu, s1, 2);
        if ((lane & 3) == 0) {
            int m0 = bm0 + wm + mi*16 + (lane >> 2);
            atomicAdd(&g_score[m0],     s0);
            atomicAdd(&g_score[m0 + 8], s1);
        }
    }
}

// ---------------- sigmoid + normalize -> attn (also zero context) ----------------
__global__ void normalize_kernel(const float* __restrict__ b_score, float* __restrict__ attn_out,
                                 int write_attn) {
    int b = blockIdx.x, t = threadIdx.x;     // 256 threads, 2048 elems
    __shared__ float red[256];
    for (int h = t; h < H_; h += 256) g_context[b*H_ + h] = 0.f;
    float bs = b_score[0];
    float sv[8];
    float local = 0.f;
    #pragma unroll
    for (int i = 0; i < 8; i++) {
        float x = g_score[b*VLEN_ + t + i*256] + bs;
        float s = 1.f / (1.f + __expf(-x));
        sv[i] = s; local += s;
    }
    red[t] = local; __syncthreads();
    #pragma unroll
    for (int o = 128; o; o >>= 1) { if (t < o) red[t] += red[t+o]; __syncthreads(); }
    float inv = 1.f / red[0];
    #pragma unroll
    for (int i = 0; i < 8; i++) {
        float a = sv[i] * inv;
        g_attn[b*VLEN_ + t + i*256] = a;
        if (write_attn) attn_out[b*VLEN_ + t + i*256] = a;
    }
}

// ---------------- context[b,h] = sum_v attn[b,v] * value[b,v,h] ----------------
__global__ void context_kernel(const float* __restrict__ value) {
    int hc = blockIdx.x, b = blockIdx.y, vs = blockIdx.z;   // (4, B, 8)
    int h = hc*256 + threadIdx.x;
    __shared__ float a_s[256];
    a_s[threadIdx.x] = g_attn[b*VLEN_ + vs*256 + threadIdx.x];
    __syncthreads();
    const float* vp = value + ((size_t)b*VLEN_ + vs*256)*H_ + h;
    float acc = 0.f;
    #pragma unroll 8
    for (int v = 0; v < 256; v++) acc += a_s[v] * vp[(size_t)v*H_];
    atomicAdd(&g_context[b*H_ + h], acc);
}

// ---------------- output[b,h] = w_out[h] . [context | query] + b_out[h] ----------------
__global__ void output_kernel(const float* __restrict__ w_out, const float* __restrict__ b_out,
                              const float* __restrict__ query, float* __restrict__ out) {
    int b = blockIdx.y;
    int warp = threadIdx.x >> 5, lane = threadIdx.x & 31;
    int h = blockIdx.x*8 + warp;
    const float* wr = w_out + (size_t)h*(2*H_);
    const float* ctx = g_context + b*H_;
    const float* q = query + b*H_;
    float acc = 0.f;
    for (int k = lane; k < H_; k += 32) acc += wr[k]*ctx[k];
    for (int k = lane; k < H_; k += 32) acc += wr[H_+k]*q[k];
    #pragma unroll
    for (int o = 16; o; o >>= 1) acc += __shfl_xor_sync(0xffffffffu, acc, o);
    if (!lane) out[b*H_ + h] = acc + b_out[h];
}

// ---------------- launch ----------------
extern "C" void kernel_launch(void* const* d_in, const int* in_sizes, int n_in,
                              void* d_out, int out_size) {
    const float* query     = (const float*)d_in[0];
    const float* value     = (const float*)d_in[1];
    const float* prev_attn = (const float*)d_in[2];
    const float* conv_w    = (const float*)d_in[3];
    const float* conv_b    = (const float*)d_in[4];
    const float* w_loc     = (const float*)d_in[5];
    const float* w_q       = (const float*)d_in[6];
    const float* w_v       = (const float*)d_in[7];
    const float* bias      = (const float*)d_in[8];
    const float* w_score   = (const float*)d_in[9];
    const float* b_score   = (const float*)d_in[10];
    const float* w_out     = (const float*)d_in[11];
    const float* b_out     = (const float*)d_in[12];
    float* out = (float*)d_out;

    (void)in_sizes; (void)n_in;

    cudaFuncSetAttribute(gemm_score_kernel,
                         cudaFuncAttributeMaxDynamicSharedMemorySize, SMEM_TOTAL_GEMM);

    build_valcat<<< (M_*(KC/8))/256, 256 >>>(value, prev_attn, conv_w, conv_b);
    build_wcat<<< (DIM_*(KC/8) + 255)/256, 256 >>>(w_v, w_loc);
    qbias_kernel<<< dim3(DIM_/8, B_), 256 >>>(query, w_q, bias);
    gemm_score_kernel<<< dim3(DIM_/BN, M_/BM), 256, SMEM_TOTAL_GEMM >>>(w_score);

    int write_attn = (out_size >= B_*H_ + M_) ? 1 : 0;   // output first, then attn
    normalize_kernel<<< B_, 256 >>>(b_score, out + B_*H_, write_attn);
    context_kernel<<< dim3(H_/256, B_, VLEN_/256), 256 >>>(value);
    output_kernel<<< dim3(H_/8, B_), 256 >>>(w_out, b_out, query, out);
}